// round 17
// baseline (speedup 1.0000x reference)
#include <cuda_runtime.h>
#include <cuda_fp16.h>
#include <stdint.h>

#define N_MAX   100000
#define E_MAX   1600000
#define E_PAD   (E_MAX + 8 * N_MAX)     // per-node segments padded to multiple of 8
#define D       64

// ---------------- scratch (static device globals; no allocations) -------------
__device__ int    g_is64;
__device__ int    g_total;
__device__ int    g_deg[N_MAX];
__device__ float  g_dinv[N_MAX];
__device__ int    g_rowstart[N_MAX];
__device__ int    g_rank[E_MAX];                  // within-segment rank per edge
__device__ float4 g_edge4[E_PAD / 2];             // {col,lap,col,lap}; 16B aligned
__device__ __half g_hx [(size_t)N_MAX * D];       // fp16 copy of x
__device__ __half g_t1 [(size_t)N_MAX * D];
__device__ __half g_t2 [(size_t)N_MAX * D];
__device__ __half g_t3 [(size_t)N_MAX * D];

// ---------------- prep -----------------------------------------------------------
__global__ void k_detect(const void* __restrict__ ei_raw, int n) {
    if (threadIdx.x == 0) { g_total = 0; g_is64 = 1; }
    __syncthreads();
    const long long* e64 = (const long long*)ei_raw;
    long long v = e64[threadIdx.x];
    if (v < 0 || v >= (long long)n) g_is64 = 0;   // any OOB => int32 data
}

// histogram + per-edge rank (atomicAdd return value IS the rank)
__global__ void k_prep(const void* __restrict__ ei_raw, int E) {
    int e = blockIdx.x * blockDim.x + threadIdx.x;
    if (e >= E) return;
    int r;
    if (g_is64) r = (int)((const long long*)ei_raw)[e];
    else        r = ((const int*)ei_raw)[e];
    g_rank[e] = atomicAdd(&g_deg[r], 1);
}

// segment allocation padded to multiple of 8; zero-fill pad slots
__global__ void k_offsets(int n) {
    int i = blockIdx.x * blockDim.x + threadIdx.x;
    if (i >= n) return;
    int dg  = g_deg[i];
    int dgp = (dg + 7) & ~7;
    int st  = atomicAdd(&g_total, dgp);
    g_rowstart[i] = st;
    g_dinv[i]     = (dg > 0) ? rsqrtf((float)dg) : 0.0f;
    float2* ge = (float2*)g_edge4;
    for (int q = dg; q < dgp; ++q)
        ge[st + q] = make_float2(0.0f, 0.0f);     // col=0, lap=0 (harmless)
}

// atomic-free scatter: slot = rowstart[r] + rank[e]
__global__ void k_scatter(const void* __restrict__ ei_raw,
                          const float* __restrict__ ea, int E) {
    int e = blockIdx.x * blockDim.x + threadIdx.x;
    if (e >= E) return;
    int r, c;
    if (g_is64) {
        const long long* ei = (const long long*)ei_raw;
        r = (int)ei[e];
        c = (int)ei[(size_t)E + e];
    } else {
        const int* ei = (const int*)ei_raw;
        r = ei[e];
        c = ei[(size_t)E + e];
    }
    int p = g_rowstart[r] + g_rank[e];
    ((float2*)g_edge4)[p] = make_float2(__int_as_float(c), ea[e] * g_dinv[c]);
}

// x (fp32) -> fp16 copy
__global__ void k_f2h(const float* __restrict__ src, int total4) {
    int i = blockIdx.x * 256 + threadIdx.x;
    if (i >= total4) return;
    float4 v = ((const float4*)src)[i];
    __half2 a = __floats2half2_rn(v.x, v.y);
    __half2 b = __floats2half2_rn(v.z, v.w);
    ((__half2*)g_hx)[i * 2 + 0] = a;
    ((__half2*)g_hx)[i * 2 + 1] = b;
}

// ---------------- SpMM: aligned float4 edge loads, 16-deep gather pipeline --------
// 2 nodes per warp, 16 lanes per node, 8B (4 halves) per lane -> 128B per row.
// 16 edges per iteration: group A unconditional, group B predicated into
// zero-init regs (pad slots {col=0,lap=0} gather row 0 harmlessly, weight 0).
template <int K>
__global__ void __launch_bounds__(256) spmm_kernel(
    const __half* __restrict__ h,
    const __half* __restrict__ prev,
    __half* __restrict__ dst,
    int n)
{
    int tid  = threadIdx.x;
    int warp = tid >> 5;
    int lane = tid & 31;
    int half = lane >> 4;
    int hl   = lane & 15;

    int r = blockIdx.x * 16 + warp * 2 + half;
    bool valid = (r < n);

    int   s = 0, mNp = 0;
    float scale = 0.0f;
    if (valid) {
        s     = g_rowstart[r];               // multiple of 8
        int d = g_deg[r];
        mNp   = (d + 7) & ~7;                // padded loop bound
        scale = -g_dinv[r];
    }

    float4 acc = make_float4(0.0f, 0.0f, 0.0f, 0.0f);
    const float4 z4 = make_float4(0.f, 0.f, 0.f, 0.f);

    for (int jb = 0; jb < mNp; jb += 16) {
        int q4 = (s + jb) >> 1;              // float4 index, aligned by construction
        // group A: edges jb..jb+7 (unconditional)
        float4 p0 = g_edge4[q4 + 0];
        float4 p1 = g_edge4[q4 + 1];
        float4 p2 = g_edge4[q4 + 2];
        float4 p3 = g_edge4[q4 + 3];
        // group B: edges jb+8..jb+15 (predicated; zeros -> harmless row-0 gathers)
        float4 p4 = z4, p5 = z4, p6 = z4, p7 = z4;
        if (jb + 8 < mNp) {
            p4 = g_edge4[q4 + 4];
            p5 = g_edge4[q4 + 5];
            p6 = g_edge4[q4 + 6];
            p7 = g_edge4[q4 + 7];
        }

        // 16 independent gathers
        uint2 u0 = *(const uint2*)(h + (size_t)__float_as_int(p0.x) * D + hl * 4);
        uint2 u1 = *(const uint2*)(h + (size_t)__float_as_int(p0.z) * D + hl * 4);
        uint2 u2 = *(const uint2*)(h + (size_t)__float_as_int(p1.x) * D + hl * 4);
        uint2 u3 = *(const uint2*)(h + (size_t)__float_as_int(p1.z) * D + hl * 4);
        uint2 u4 = *(const uint2*)(h + (size_t)__float_as_int(p2.x) * D + hl * 4);
        uint2 u5 = *(const uint2*)(h + (size_t)__float_as_int(p2.z) * D + hl * 4);
        uint2 u6 = *(const uint2*)(h + (size_t)__float_as_int(p3.x) * D + hl * 4);
        uint2 u7 = *(const uint2*)(h + (size_t)__float_as_int(p3.z) * D + hl * 4);
        uint2 u8 = *(const uint2*)(h + (size_t)__float_as_int(p4.x) * D + hl * 4);
        uint2 u9 = *(const uint2*)(h + (size_t)__float_as_int(p4.z) * D + hl * 4);
        uint2 uA = *(const uint2*)(h + (size_t)__float_as_int(p5.x) * D + hl * 4);
        uint2 uB = *(const uint2*)(h + (size_t)__float_as_int(p5.z) * D + hl * 4);
        uint2 uC = *(const uint2*)(h + (size_t)__float_as_int(p6.x) * D + hl * 4);
        uint2 uD = *(const uint2*)(h + (size_t)__float_as_int(p6.z) * D + hl * 4);
        uint2 uE = *(const uint2*)(h + (size_t)__float_as_int(p7.x) * D + hl * 4);
        uint2 uF = *(const uint2*)(h + (size_t)__float_as_int(p7.z) * D + hl * 4);

#define ACC(ui, lw)                                                     \
        {                                                               \
            float2 f0 = __half22float2(*(__half2*)&ui.x);               \
            float2 f1 = __half22float2(*(__half2*)&ui.y);               \
            acc.x = fmaf(lw, f0.x, acc.x);                              \
            acc.y = fmaf(lw, f0.y, acc.y);                              \
            acc.z = fmaf(lw, f1.x, acc.z);                              \
            acc.w = fmaf(lw, f1.y, acc.w);                              \
        }
        ACC(u0, p0.y) ACC(u1, p0.w) ACC(u2, p1.y) ACC(u3, p1.w)
        ACC(u4, p2.y) ACC(u5, p2.w) ACC(u6, p3.y) ACC(u7, p3.w)
        ACC(u8, p4.y) ACC(u9, p4.w) ACC(uA, p5.y) ACC(uB, p5.w)
        ACC(uC, p6.y) ACC(uD, p6.w) ACC(uE, p7.y) ACC(uF, p7.w)
#undef ACC
    }

    if (!valid) return;

    float4 t;
    if constexpr (K == 1) {
        t = make_float4(scale * acc.x, scale * acc.y, scale * acc.z, scale * acc.w);
    } else {
        uint2 pu = *(const uint2*)(prev + (size_t)r * D + hl * 4);
        float2 p0 = __half22float2(*(__half2*)&pu.x);
        float2 p1 = __half22float2(*(__half2*)&pu.y);
        float s2 = 2.0f * scale;
        t = make_float4(fmaf(s2, acc.x, -p0.x), fmaf(s2, acc.y, -p0.y),
                        fmaf(s2, acc.z, -p1.x), fmaf(s2, acc.w, -p1.y));
    }
    __half2 o0 = __floats2half2_rn(t.x, t.y);
    __half2 o1 = __floats2half2_rn(t.z, t.w);
    uint2 st = make_uint2(*(uint32_t*)&o0, *(uint32_t*)&o1);
    *(uint2*)(dst + (size_t)r * D + hl * 4) = st;
}

// ---------------- TF32 tensor GEMM: out = [x|T1|T2|T3] @ W(256x64) + bias ---------
#define GROWS 128

__device__ __forceinline__ uint32_t f2tf(float f) {
    uint32_t r;
    asm("cvt.rna.tf32.f32 %0, %1;" : "=r"(r) : "f"(f));
    return r;
}

__global__ void __launch_bounds__(256) gemm_tf32(
    const float* __restrict__ w,      // [4][64][64] stacked
    const float* __restrict__ bias,
    float* __restrict__ out,
    int n)
{
    __shared__ uint32_t sA[GROWS][36];
    __shared__ uint32_t sW[32][72];

    int tid  = threadIdx.x;
    int lane = tid & 31;
    int warp = tid >> 5;
    int g    = lane >> 2;
    int tg   = lane & 3;
    int base = blockIdx.x * GROWS;

    float c[8][4];
#pragma unroll
    for (int j = 0; j < 8; ++j)
#pragma unroll
        for (int i = 0; i < 4; ++i) c[j][i] = 0.0f;

    const __half* srcs[4] = { g_hx, g_t1, g_t2, g_t3 };

#pragma unroll
    for (int chunk = 0; chunk < 4; ++chunk) {
        const __half* src = srcs[chunk];
        const float*  wc  = w + chunk * (D * D);
#pragma unroll
        for (int h = 0; h < 2; ++h) {
            __syncthreads();
#pragma unroll
            for (int i = 0; i < 2; ++i) {
                int i4 = tid + i * 256;
                float4 v = *(const float4*)(wc + h * 2048 + i4 * 4);
                int k   = i4 >> 4;
                int col = (i4 & 15) * 4;
                sW[k][col + 0] = f2tf(v.x);
                sW[k][col + 1] = f2tf(v.y);
                sW[k][col + 2] = f2tf(v.z);
                sW[k][col + 3] = f2tf(v.w);
            }
            {
                int m      = tid >> 1;
                int half16 = (tid & 1) << 4;
                int row    = base + m;
                const __half* sp = src + (size_t)row * D + h * 32 + half16;
                uint4 u0 = make_uint4(0, 0, 0, 0), u1 = make_uint4(0, 0, 0, 0);
                if (row < n) {
                    u0 = *(const uint4*)sp;
                    u1 = *(const uint4*)(sp + 8);
                }
#pragma unroll
                for (int q = 0; q < 8; ++q) {
                    uint32_t pk = (q < 4) ? (&u0.x)[q] : (&u1.x)[q - 4];
                    float2 f = __half22float2(*(__half2*)&pk);
                    sA[m][half16 + q * 2 + 0] = f2tf(f.x);
                    sA[m][half16 + q * 2 + 1] = f2tf(f.y);
                }
            }
            __syncthreads();

#pragma unroll
            for (int k0 = 0; k0 < 32; k0 += 8) {
                uint32_t a0 = sA[warp * 16 + g    ][k0 + tg];
                uint32_t a1 = sA[warp * 16 + g + 8][k0 + tg];
                uint32_t a2 = sA[warp * 16 + g    ][k0 + tg + 4];
                uint32_t a3 = sA[warp * 16 + g + 8][k0 + tg + 4];
#pragma unroll
                for (int j = 0; j < 8; ++j) {
                    uint32_t b0 = sW[k0 + tg    ][j * 8 + g];
                    uint32_t b1 = sW[k0 + tg + 4][j * 8 + g];
                    asm volatile(
                        "mma.sync.aligned.m16n8k8.row.col.f32.tf32.tf32.f32 "
                        "{%0,%1,%2,%3}, {%4,%5,%6,%7}, {%8,%9}, {%0,%1,%2,%3};"
                        : "+f"(c[j][0]), "+f"(c[j][1]), "+f"(c[j][2]), "+f"(c[j][3])
                        : "r"(a0), "r"(a1), "r"(a2), "r"(a3), "r"(b0), "r"(b1));
                }
            }
        }
    }

    int r0 = base + warp * 16 + g;
    int r1 = r0 + 8;
#pragma unroll
    for (int j = 0; j < 8; ++j) {
        int col  = j * 8 + tg * 2;
        float bx = __ldg(bias + col);
        float by = __ldg(bias + col + 1);
        if (r0 < n) {
            float2 v = make_float2(c[j][0] + bx, c[j][1] + by);
            *(float2*)(out + (size_t)r0 * D + col) = v;
        }
        if (r1 < n) {
            float2 v = make_float2(c[j][2] + bx, c[j][3] + by);
            *(float2*)(out + (size_t)r1 * D + col) = v;
        }
    }
}

// ---------------- launch -----------------------------------------------------------
extern "C" void kernel_launch(void* const* d_in, const int* in_sizes, int n_in,
                              void* d_out, int out_size)
{
    const float* x   = (const float*)d_in[0];
    const void*  ei  = d_in[1];
    const float* ea  = (const float*)d_in[2];
    const float* w   = (const float*)d_in[3];
    const float* b   = (const float*)d_in[4];
    float*       out = (float*)d_out;

    int n = in_sizes[0] / D;
    int E = in_sizes[2];

    int nbN = (n + 255) / 256;
    int nbE = (E + 255) / 256;

    __half *hx, *t1, *t2, *t3;
    cudaGetSymbolAddress((void**)&hx, g_hx);
    cudaGetSymbolAddress((void**)&t1, g_t1);
    cudaGetSymbolAddress((void**)&t2, g_t2);
    cudaGetSymbolAddress((void**)&t3, g_t3);

    void* degp; cudaGetSymbolAddress(&degp, g_deg);
    cudaMemsetAsync(degp, 0, (size_t)n * sizeof(int));

    k_detect<<<1, 256>>>(ei, n);
    k_f2h<<<(n * (D / 4) + 255) / 256, 256>>>(x, n * (D / 4));
    k_prep<<<nbE, 256>>>(ei, E);
    k_offsets<<<nbN, 256>>>(n);
    k_scatter<<<nbE, 256>>>(ei, ea, E);

    int gs = (n + 15) / 16;   // 16 nodes per block (2 per warp)
    spmm_kernel<1><<<gs, 256>>>(hx, nullptr, t1, n);
    spmm_kernel<2><<<gs, 256>>>(t1, hx,      t2, n);
    spmm_kernel<3><<<gs, 256>>>(t2, t1,      t3, n);

    gemm_tf32<<<(n + GROWS - 1) / GROWS, 256>>>(w, b, out, n);
}